// round 1
// baseline (speedup 1.0000x reference)
#include <cuda_runtime.h>

#define BATCHN   131072
#define SDIM     137
#define W0COLS   139
#define HID      256
#define AHD      128
#define NBLK     4
#define ROWS     64
#define NTHREADS 256
#define SSTRIDE  144   // padded state row stride (16B aligned)

#define SMEM_FLOATS (2*ROWS*HID + ROWS*SSTRIDE)
#define SMEM_BYTES  (SMEM_FLOATS * 4)

// ---- small precomputed scratch (device globals: no allocation allowed) ----
__device__ float g_b0p[HID];        // b0 + sin*W0[:,137] + cos*W0[:,138]
__device__ float g_Mta[AHD*AHD];    // ta_out_w @ Wv_ta
__device__ float g_cta[AHD];        // ta_out_w @ bv_ta + ta_out_b
__device__ float g_Mlm[64];         // lm_out_w @ Wv_lm  (8x8)
__device__ float g_clm[8];

__global__ void prep1(const float* __restrict__ t, const float* __restrict__ W0,
                      const float* __restrict__ b0,
                      const float* __restrict__ lm_in_w, const float* __restrict__ lm_in_b,
                      const float* __restrict__ lm_out_w, const float* __restrict__ lm_out_b,
                      const float* __restrict__ ta_in_b,
                      const float* __restrict__ ta_out_w, const float* __restrict__ ta_out_b) {
    int tid = threadIdx.x;
    float ang = t[0] * (2.0f * 3.14159265358979323846f / 24.0f);
    float sv = sinf(ang), cv = cosf(ang);
    if (tid < HID)
        g_b0p[tid] = b0[tid] + sv * W0[tid*W0COLS + 137] + cv * W0[tid*W0COLS + 138];
    if (tid < 64) {
        int i = tid >> 3, j = tid & 7;
        float a = 0.f;
        #pragma unroll
        for (int k = 0; k < 8; k++) a += lm_out_w[i*8+k] * lm_in_w[(16+k)*8 + j];
        g_Mlm[tid] = a;
    }
    if (tid < 8) {
        float a = lm_out_b[tid];
        #pragma unroll
        for (int k = 0; k < 8; k++) a += lm_out_w[tid*8+k] * lm_in_b[16+k];
        g_clm[tid] = a;
    }
    if (tid < AHD) {
        float a = ta_out_b[tid];
        for (int k = 0; k < AHD; k++) a += ta_out_w[tid*AHD+k] * ta_in_b[2*AHD+k];
        g_cta[tid] = a;
    }
}

__global__ void prep2(const float* __restrict__ ta_in_w,
                      const float* __restrict__ ta_out_w) {
    int idx = blockIdx.x * blockDim.x + threadIdx.x;  // 64*256 = 16384 = 128*128
    int i = idx >> 7, j = idx & 127;
    float a = 0.f;
    for (int k = 0; k < AHD; k++)
        a += ta_out_w[i*AHD + k] * ta_in_w[(2*AHD + k)*AHD + j];
    g_Mta[idx] = a;
}

// 64x256 tile GEMM step: acc[rr][j] += sum_k src[rbase+rr][k] * W[tx+32j][k]
__device__ __forceinline__ void gemm_tile(const float* __restrict__ src, int srcStride,
                                          const float* __restrict__ W,
                                          int rbase, int tx, float acc[8][8]) {
    #pragma unroll 1
    for (int k = 0; k < HID; k += 4) {
        float4 hv[8];
        #pragma unroll
        for (int rr = 0; rr < 8; rr++)
            hv[rr] = *reinterpret_cast<const float4*>(&src[(rbase+rr)*srcStride + k]);
        float4 wv[8];
        #pragma unroll
        for (int j = 0; j < 8; j++)
            wv[j] = *reinterpret_cast<const float4*>(&W[(tx + 32*j)*HID + k]);
        #pragma unroll
        for (int j = 0; j < 8; j++) {
            #pragma unroll
            for (int rr = 0; rr < 8; rr++) {
                acc[rr][j] = fmaf(hv[rr].x, wv[j].x, acc[rr][j]);
                acc[rr][j] = fmaf(hv[rr].y, wv[j].y, acc[rr][j]);
                acc[rr][j] = fmaf(hv[rr].z, wv[j].z, acc[rr][j]);
                acc[rr][j] = fmaf(hv[rr].w, wv[j].w, acc[rr][j]);
            }
        }
    }
}

extern "C" __global__ void __launch_bounds__(NTHREADS, 1)
ode_main(const float* __restrict__ state,
         const float* __restrict__ W0,
         const float* __restrict__ blkW1, const float* __restrict__ blkb1,
         const float* __restrict__ blkW2, const float* __restrict__ blkb2,
         const float* __restrict__ Wout, const float* __restrict__ bout,
         float* __restrict__ out) {
    extern __shared__ float smem[];
    float* s_h = smem;                  // [ROWS][HID]
    float* s_t = smem + ROWS*HID;       // [ROWS][HID]
    float* s_s = smem + 2*ROWS*HID;     // [ROWS][SSTRIDE] (state tile)

    const int tid = threadIdx.x;
    const int tx = tid & 31;
    const int ty = tid >> 5;
    const int rbase = ty * 8;
    const int row0 = blockIdx.x * ROWS;

    // load state tile (coalesced)
    for (int i = tid; i < ROWS*SDIM; i += NTHREADS) {
        int r = i / SDIM;
        int k = i - r*SDIM;
        s_s[r*SSTRIDE + k] = state[(size_t)(row0 + r)*SDIM + k];
    }
    __syncthreads();

    float acc[8][8];

    // ---- layer 0: h = relu(state @ W0[:, :137]^T + b0p), K = 137 ----
    #pragma unroll
    for (int rr = 0; rr < 8; rr++)
        #pragma unroll
        for (int j = 0; j < 8; j++) acc[rr][j] = 0.f;

    #pragma unroll 1
    for (int k = 0; k < SDIM; k++) {
        float hv[8];
        #pragma unroll
        for (int rr = 0; rr < 8; rr++) hv[rr] = s_s[(rbase+rr)*SSTRIDE + k];
        float wv[8];
        #pragma unroll
        for (int j = 0; j < 8; j++) wv[j] = W0[(tx + 32*j)*W0COLS + k];
        #pragma unroll
        for (int j = 0; j < 8; j++)
            #pragma unroll
            for (int rr = 0; rr < 8; rr++)
                acc[rr][j] = fmaf(hv[rr], wv[j], acc[rr][j]);
    }
    #pragma unroll
    for (int j = 0; j < 8; j++) {
        int c = tx + 32*j;
        float b = g_b0p[c];
        #pragma unroll
        for (int rr = 0; rr < 8; rr++)
            s_h[(rbase+rr)*HID + c] = fmaxf(acc[rr][j] + b, 0.f);
    }
    __syncthreads();

    // ---- 4 residual blocks ----
    #pragma unroll 1
    for (int blk = 0; blk < NBLK; blk++) {
        const float* W1 = blkW1 + blk*HID*HID;
        const float* b1 = blkb1 + blk*HID;
        #pragma unroll
        for (int rr = 0; rr < 8; rr++)
            #pragma unroll
            for (int j = 0; j < 8; j++) acc[rr][j] = 0.f;
        gemm_tile(s_h, HID, W1, rbase, tx, acc);
        #pragma unroll
        for (int j = 0; j < 8; j++) {
            int c = tx + 32*j;
            float b = b1[c];
            #pragma unroll
            for (int rr = 0; rr < 8; rr++)
                s_t[(rbase+rr)*HID + c] = tanhf(acc[rr][j] + b);
        }
        __syncthreads();

        const float* W2 = blkW2 + blk*HID*HID;
        const float* b2 = blkb2 + blk*HID;
        #pragma unroll
        for (int rr = 0; rr < 8; rr++)
            #pragma unroll
            for (int j = 0; j < 8; j++) acc[rr][j] = 0.f;
        gemm_tile(s_t, HID, W2, rbase, tx, acc);
        // safe: all reads of s_h (pass A) completed before the sync above;
        // each thread writes only its own s_h elements here.
        #pragma unroll
        for (int j = 0; j < 8; j++) {
            int c = tx + 32*j;
            float b = b2[c];
            #pragma unroll
            for (int rr = 0; rr < 8; rr++) {
                float hold = s_h[(rbase+rr)*HID + c];
                s_h[(rbase+rr)*HID + c] = tanhf(hold + acc[rr][j] + b);
            }
        }
        __syncthreads();
    }

    // ---- output projection (cols 0..136) + delta path ----
    float accc[8][4];
    float acc5[8];
    float accd[8][4];
    #pragma unroll
    for (int rr = 0; rr < 8; rr++) {
        acc5[rr] = 0.f;
        #pragma unroll
        for (int j = 0; j < 4; j++) { accc[rr][j] = 0.f; accd[rr][j] = 0.f; }
    }
    const bool has5 = (tx < 9);
    const int c5 = tx + 128;

    #pragma unroll 1
    for (int k = 0; k < HID; k += 4) {
        float4 hv[8];
        #pragma unroll
        for (int rr = 0; rr < 8; rr++)
            hv[rr] = *reinterpret_cast<const float4*>(&s_h[(rbase+rr)*HID + k]);
        float4 wv[4];
        #pragma unroll
        for (int j = 0; j < 4; j++)
            wv[j] = *reinterpret_cast<const float4*>(&Wout[(tx + 32*j)*HID + k]);
        float4 w5 = make_float4(0.f, 0.f, 0.f, 0.f);
        if (has5) w5 = *reinterpret_cast<const float4*>(&Wout[c5*HID + k]);
        #pragma unroll
        for (int j = 0; j < 4; j++) {
            #pragma unroll
            for (int rr = 0; rr < 8; rr++) {
                accc[rr][j] = fmaf(hv[rr].x, wv[j].x, accc[rr][j]);
                accc[rr][j] = fmaf(hv[rr].y, wv[j].y, accc[rr][j]);
                accc[rr][j] = fmaf(hv[rr].z, wv[j].z, accc[rr][j]);
                accc[rr][j] = fmaf(hv[rr].w, wv[j].w, accc[rr][j]);
            }
        }
        #pragma unroll
        for (int rr = 0; rr < 8; rr++) {
            acc5[rr] = fmaf(hv[rr].x, w5.x, acc5[rr]);
            acc5[rr] = fmaf(hv[rr].y, w5.y, acc5[rr]);
            acc5[rr] = fmaf(hv[rr].z, w5.z, acc5[rr]);
            acc5[rr] = fmaf(hv[rr].w, w5.w, acc5[rr]);
        }
    }

    // delta_h GEMM: hs @ M_ta^T, K = 128, cols 0..127 (= tx + 32j, j<4)
    #pragma unroll 1
    for (int k = 0; k < AHD; k += 4) {
        float4 sv[8];
        #pragma unroll
        for (int rr = 0; rr < 8; rr++)
            sv[rr] = *reinterpret_cast<const float4*>(&s_s[(rbase+rr)*SSTRIDE + k]);
        float4 mv[4];
        #pragma unroll
        for (int j = 0; j < 4; j++)
            mv[j] = *reinterpret_cast<const float4*>(&g_Mta[(tx + 32*j)*AHD + k]);
        #pragma unroll
        for (int j = 0; j < 4; j++) {
            #pragma unroll
            for (int rr = 0; rr < 8; rr++) {
                accd[rr][j] = fmaf(sv[rr].x, mv[j].x, accd[rr][j]);
                accd[rr][j] = fmaf(sv[rr].y, mv[j].y, accd[rr][j]);
                accd[rr][j] = fmaf(sv[rr].z, mv[j].z, accd[rr][j]);
                accd[rr][j] = fmaf(sv[rr].w, mv[j].w, accd[rr][j]);
            }
        }
    }

    // ---- write outputs ----
    #pragma unroll
    for (int j = 0; j < 4; j++) {
        int c = tx + 32*j;
        float bo = bout[c];
        float ct = g_cta[c];
        #pragma unroll
        for (int rr = 0; rr < 8; rr++) {
            int r = rbase + rr;
            float core = accc[rr][j] + bo;
            float d = accd[rr][j] + ct - s_s[r*SSTRIDE + c];
            out[(size_t)(row0 + r)*SDIM + c] = core + 0.1f * d;
        }
    }
    if (has5) {
        float bo = bout[c5];
        if (c5 < 136) {
            int lm = c5 - 128;
            float cl = g_clm[lm];
            float m[8];
            #pragma unroll
            for (int mm = 0; mm < 8; mm++) m[mm] = g_Mlm[lm*8 + mm];
            #pragma unroll
            for (int rr = 0; rr < 8; rr++) {
                int r = rbase + rr;
                float d = cl - s_s[r*SSTRIDE + c5];
                #pragma unroll
                for (int mm = 0; mm < 8; mm++)
                    d += m[mm] * s_s[r*SSTRIDE + 128 + mm];
                out[(size_t)(row0 + r)*SDIM + c5] = acc5[rr] + bo + 0.1f * d;
            }
        } else {  // c5 == 136: movement channel, delta = 0
            #pragma unroll
            for (int rr = 0; rr < 8; rr++) {
                int r = rbase + rr;
                out[(size_t)(row0 + r)*SDIM + c5] = acc5[rr] + bo;
            }
        }
    }
}

extern "C" void kernel_launch(void* const* d_in, const int* in_sizes, int n_in,
                              void* d_out, int out_size) {
    const float* t        = (const float*)d_in[0];
    const float* state    = (const float*)d_in[1];
    const float* W0       = (const float*)d_in[2];
    const float* b0       = (const float*)d_in[3];
    const float* blkW1    = (const float*)d_in[4];
    const float* blkb1    = (const float*)d_in[5];
    const float* blkW2    = (const float*)d_in[6];
    const float* blkb2    = (const float*)d_in[7];
    const float* Wout     = (const float*)d_in[8];
    const float* bout     = (const float*)d_in[9];
    const float* lm_in_w  = (const float*)d_in[10];
    const float* lm_in_b  = (const float*)d_in[11];
    const float* lm_out_w = (const float*)d_in[12];
    const float* lm_out_b = (const float*)d_in[13];
    const float* ta_in_w  = (const float*)d_in[14];
    const float* ta_in_b  = (const float*)d_in[15];
    const float* ta_out_w = (const float*)d_in[16];
    const float* ta_out_b = (const float*)d_in[17];
    float* out = (float*)d_out;

    cudaFuncSetAttribute(ode_main, cudaFuncAttributeMaxDynamicSharedMemorySize, SMEM_BYTES);

    prep1<<<1, 256>>>(t, W0, b0, lm_in_w, lm_in_b, lm_out_w, lm_out_b,
                      ta_in_b, ta_out_w, ta_out_b);
    prep2<<<64, 256>>>(ta_in_w, ta_out_w);
    ode_main<<<BATCHN / ROWS, NTHREADS, SMEM_BYTES>>>(
        state, W0, blkW1, blkb1, blkW2, blkb2, Wout, bout, out);
}

// round 2
// speedup vs baseline: 1.0593x; 1.0593x over previous
#include <cuda_runtime.h>

#define BATCHN   131072
#define SDIM     137
#define W0COLS   139
#define HID      256
#define AHD      128
#define NBLK     4
#define ROWS     64
#define NTHREADS 256
#define SSTRIDE  144   // padded state row stride (16B aligned)

#define SMEM_FLOATS (2*ROWS*HID + ROWS*SSTRIDE)
#define SMEM_BYTES  (SMEM_FLOATS * 4)

// ---- small precomputed scratch (device globals: no allocation allowed) ----
__device__ float g_b0p[HID];        // b0 + sin*W0[:,137] + cos*W0[:,138]
__device__ float g_Mta[AHD*AHD];    // ta_out_w @ Wv_ta
__device__ float g_cta[AHD];        // ta_out_w @ bv_ta + ta_out_b
__device__ float g_Mlm[64];         // lm_out_w @ Wv_lm  (8x8)
__device__ float g_clm[8];

__global__ void prep1(const float* __restrict__ t, const float* __restrict__ W0,
                      const float* __restrict__ b0,
                      const float* __restrict__ lm_in_w, const float* __restrict__ lm_in_b,
                      const float* __restrict__ lm_out_w, const float* __restrict__ lm_out_b,
                      const float* __restrict__ ta_in_b,
                      const float* __restrict__ ta_out_w, const float* __restrict__ ta_out_b) {
    int tid = threadIdx.x;
    float ang = t[0] * (2.0f * 3.14159265358979323846f / 24.0f);
    float sv = sinf(ang), cv = cosf(ang);
    if (tid < HID)
        g_b0p[tid] = b0[tid] + sv * W0[tid*W0COLS + 137] + cv * W0[tid*W0COLS + 138];
    if (tid < 64) {
        int i = tid >> 3, j = tid & 7;
        float a = 0.f;
        #pragma unroll
        for (int k = 0; k < 8; k++) a += lm_out_w[i*8+k] * lm_in_w[(16+k)*8 + j];
        g_Mlm[tid] = a;
    }
    if (tid < 8) {
        float a = lm_out_b[tid];
        #pragma unroll
        for (int k = 0; k < 8; k++) a += lm_out_w[tid*8+k] * lm_in_b[16+k];
        g_clm[tid] = a;
    }
    if (tid < AHD) {
        float a = ta_out_b[tid];
        for (int k = 0; k < AHD; k++) a += ta_out_w[tid*AHD+k] * ta_in_b[2*AHD+k];
        g_cta[tid] = a;
    }
}

__global__ void prep2(const float* __restrict__ ta_in_w,
                      const float* __restrict__ ta_out_w) {
    int idx = blockIdx.x * blockDim.x + threadIdx.x;  // 64*256 = 16384 = 128*128
    int i = idx >> 7, j = idx & 127;
    float a = 0.f;
    for (int k = 0; k < AHD; k++)
        a += ta_out_w[i*AHD + k] * ta_in_w[(2*AHD + k)*AHD + j];
    g_Mta[idx] = a;
}

// 64x256 tile GEMM step: acc[rr][j] += sum_k src[rbase+rr][k] * W[tx+32j][k]
__device__ __forceinline__ void gemm_tile(const float* __restrict__ src, int srcStride,
                                          const float* __restrict__ W,
                                          int rbase, int tx, float acc[8][8]) {
    #pragma unroll 1
    for (int k = 0; k < HID; k += 4) {
        float4 hv[8];
        #pragma unroll
        for (int rr = 0; rr < 8; rr++)
            hv[rr] = *reinterpret_cast<const float4*>(&src[(rbase+rr)*srcStride + k]);
        float4 wv[8];
        #pragma unroll
        for (int j = 0; j < 8; j++)
            wv[j] = *reinterpret_cast<const float4*>(&W[(tx + 32*j)*HID + k]);
        #pragma unroll
        for (int j = 0; j < 8; j++) {
            #pragma unroll
            for (int rr = 0; rr < 8; rr++) {
                acc[rr][j] = fmaf(hv[rr].x, wv[j].x, acc[rr][j]);
                acc[rr][j] = fmaf(hv[rr].y, wv[j].y, acc[rr][j]);
                acc[rr][j] = fmaf(hv[rr].z, wv[j].z, acc[rr][j]);
                acc[rr][j] = fmaf(hv[rr].w, wv[j].w, acc[rr][j]);
            }
        }
    }
}

extern "C" __global__ void __launch_bounds__(NTHREADS, 1)
ode_main(const float* __restrict__ state,
         const float* __restrict__ W0,
         const float* __restrict__ blkW1, const float* __restrict__ blkb1,
         const float* __restrict__ blkW2, const float* __restrict__ blkb2,
         const float* __restrict__ Wout, const float* __restrict__ bout,
         float* __restrict__ out) {
    extern __shared__ float smem[];
    float* s_h = smem;                  // [ROWS][HID]
    float* s_t = smem + ROWS*HID;       // [ROWS][HID]
    float* s_s = smem + 2*ROWS*HID;     // [ROWS][SSTRIDE] (state tile)

    const int tid = threadIdx.x;
    const int tx = tid & 31;
    const int ty = tid >> 5;
    const int rbase = ty * 8;
    const int row0 = blockIdx.x * ROWS;

    // load state tile (coalesced)
    for (int i = tid; i < ROWS*SDIM; i += NTHREADS) {
        int r = i / SDIM;
        int k = i - r*SDIM;
        s_s[r*SSTRIDE + k] = state[(size_t)(row0 + r)*SDIM + k];
    }
    __syncthreads();

    float acc[8][8];

    // ---- layer 0: h = relu(state @ W0[:, :137]^T + b0p), K = 137 ----
    #pragma unroll
    for (int rr = 0; rr < 8; rr++)
        #pragma unroll
        for (int j = 0; j < 8; j++) acc[rr][j] = 0.f;

    #pragma unroll 1
    for (int k = 0; k < SDIM; k++) {
        float hv[8];
        #pragma unroll
        for (int rr = 0; rr < 8; rr++) hv[rr] = s_s[(rbase+rr)*SSTRIDE + k];
        float wv[8];
        #pragma unroll
        for (int j = 0; j < 8; j++) wv[j] = W0[(tx + 32*j)*W0COLS + k];
        #pragma unroll
        for (int j = 0; j < 8; j++)
            #pragma unroll
            for (int rr = 0; rr < 8; rr++)
                acc[rr][j] = fmaf(hv[rr], wv[j], acc[rr][j]);
    }
    #pragma unroll
    for (int j = 0; j < 8; j++) {
        int c = tx + 32*j;
        float b = g_b0p[c];
        #pragma unroll
        for (int rr = 0; rr < 8; rr++)
            s_h[(rbase+rr)*HID + c] = fmaxf(acc[rr][j] + b, 0.f);
    }
    __syncthreads();

    // ---- 4 residual blocks ----
    #pragma unroll 1
    for (int blk = 0; blk < NBLK; blk++) {
        const float* W1 = blkW1 + blk*HID*HID;
        const float* b1 = blkb1 + blk*HID;
        #pragma unroll
        for (int rr = 0; rr < 8; rr++)
            #pragma unroll
            for (int j = 0; j < 8; j++) acc[rr][j] = 0.f;
        gemm_tile(s_h, HID, W1, rbase, tx, acc);
        #pragma unroll
        for (int j = 0; j < 8; j++) {
            int c = tx + 32*j;
            float b = b1[c];
            #pragma unroll
            for (int rr = 0; rr < 8; rr++)
                s_t[(rbase+rr)*HID + c] = tanhf(acc[rr][j] + b);
        }
        __syncthreads();

        const float* W2 = blkW2 + blk*HID*HID;
        const float* b2 = blkb2 + blk*HID;
        #pragma unroll
        for (int rr = 0; rr < 8; rr++)
            #pragma unroll
            for (int j = 0; j < 8; j++) acc[rr][j] = 0.f;
        gemm_tile(s_t, HID, W2, rbase, tx, acc);
        // safe: all reads of s_h (pass A) completed before the sync above;
        // each thread writes only its own s_h elements here.
        #pragma unroll
        for (int j = 0; j < 8; j++) {
            int c = tx + 32*j;
            float b = b2[c];
            #pragma unroll
            for (int rr = 0; rr < 8; rr++) {
                float hold = s_h[(rbase+rr)*HID + c];
                s_h[(rbase+rr)*HID + c] = tanhf(hold + acc[rr][j] + b);
            }
        }
        __syncthreads();
    }

    // ---- output projection (cols 0..136) + delta path ----
    float accc[8][4];
    float acc5[8];
    float accd[8][4];
    #pragma unroll
    for (int rr = 0; rr < 8; rr++) {
        acc5[rr] = 0.f;
        #pragma unroll
        for (int j = 0; j < 4; j++) { accc[rr][j] = 0.f; accd[rr][j] = 0.f; }
    }
    const bool has5 = (tx < 9);
    const int c5 = tx + 128;

    #pragma unroll 1
    for (int k = 0; k < HID; k += 4) {
        float4 hv[8];
        #pragma unroll
        for (int rr = 0; rr < 8; rr++)
            hv[rr] = *reinterpret_cast<const float4*>(&s_h[(rbase+rr)*HID + k]);
        float4 wv[4];
        #pragma unroll
        for (int j = 0; j < 4; j++)
            wv[j] = *reinterpret_cast<const float4*>(&Wout[(tx + 32*j)*HID + k]);
        float4 w5 = make_float4(0.f, 0.f, 0.f, 0.f);
        if (has5) w5 = *reinterpret_cast<const float4*>(&Wout[c5*HID + k]);
        #pragma unroll
        for (int j = 0; j < 4; j++) {
            #pragma unroll
            for (int rr = 0; rr < 8; rr++) {
                accc[rr][j] = fmaf(hv[rr].x, wv[j].x, accc[rr][j]);
                accc[rr][j] = fmaf(hv[rr].y, wv[j].y, accc[rr][j]);
                accc[rr][j] = fmaf(hv[rr].z, wv[j].z, accc[rr][j]);
                accc[rr][j] = fmaf(hv[rr].w, wv[j].w, accc[rr][j]);
            }
        }
        #pragma unroll
        for (int rr = 0; rr < 8; rr++) {
            acc5[rr] = fmaf(hv[rr].x, w5.x, acc5[rr]);
            acc5[rr] = fmaf(hv[rr].y, w5.y, acc5[rr]);
            acc5[rr] = fmaf(hv[rr].z, w5.z, acc5[rr]);
            acc5[rr] = fmaf(hv[rr].w, w5.w, acc5[rr]);
        }
    }

    // delta_h GEMM: hs @ M_ta^T, K = 128, cols 0..127 (= tx + 32j, j<4)
    #pragma unroll 1
    for (int k = 0; k < AHD; k += 4) {
        float4 sv[8];
        #pragma unroll
        for (int rr = 0; rr < 8; rr++)
            sv[rr] = *reinterpret_cast<const float4*>(&s_s[(rbase+rr)*SSTRIDE + k]);
        float4 mv[4];
        #pragma unroll
        for (int j = 0; j < 4; j++)
            mv[j] = *reinterpret_cast<const float4*>(&g_Mta[(tx + 32*j)*AHD + k]);
        #pragma unroll
        for (int j = 0; j < 4; j++) {
            #pragma unroll
            for (int rr = 0; rr < 8; rr++) {
                accd[rr][j] = fmaf(sv[rr].x, mv[j].x, accd[rr][j]);
                accd[rr][j] = fmaf(sv[rr].y, mv[j].y, accd[rr][j]);
                accd[rr][j] = fmaf(sv[rr].z, mv[j].z, accd[rr][j]);
                accd[rr][j] = fmaf(sv[rr].w, mv[j].w, accd[rr][j]);
            }
        }
    }

    // ---- write outputs ----
    #pragma unroll
    for (int j = 0; j < 4; j++) {
        int c = tx + 32*j;
        float bo = bout[c];
        float ct = g_cta[c];
        #pragma unroll
        for (int rr = 0; rr < 8; rr++) {
            int r = rbase + rr;
            float core = accc[rr][j] + bo;
            float d = accd[rr][j] + ct - s_s[r*SSTRIDE + c];
            out[(size_t)(row0 + r)*SDIM + c] = core + 0.1f * d;
        }
    }
    if (has5) {
        float bo = bout[c5];
        if (c5 < 136) {
            int lm = c5 - 128;
            float cl = g_clm[lm];
            float m[8];
            #pragma unroll
            for (int mm = 0; mm < 8; mm++) m[mm] = g_Mlm[lm*8 + mm];
            #pragma unroll
            for (int rr = 0; rr < 8; rr++) {
                int r = rbase + rr;
                float d = cl - s_s[r*SSTRIDE + c5];
                #pragma unroll
                for (int mm = 0; mm < 8; mm++)
                    d += m[mm] * s_s[r*SSTRIDE + 128 + mm];
                out[(size_t)(row0 + r)*SDIM + c5] = acc5[rr] + bo + 0.1f * d;
            }
        } else {  // c5 == 136: movement channel, delta = 0
            #pragma unroll
            for (int rr = 0; rr < 8; rr++) {
                int r = rbase + rr;
                out[(size_t)(row0 + r)*SDIM + c5] = acc5[rr] + bo;
            }
        }
    }
}

extern "C" void kernel_launch(void* const* d_in, const int* in_sizes, int n_in,
                              void* d_out, int out_size) {
    const float* t        = (const float*)d_in[0];
    const float* state    = (const float*)d_in[1];
    const float* W0       = (const float*)d_in[2];
    const float* b0       = (const float*)d_in[3];
    const float* blkW1    = (const float*)d_in[4];
    const float* blkb1    = (const float*)d_in[5];
    const float* blkW2    = (const float*)d_in[6];
    const float* blkb2    = (const float*)d_in[7];
    const float* Wout     = (const float*)d_in[8];
    const float* bout     = (const float*)d_in[9];
    const float* lm_in_w  = (const float*)d_in[10];
    const float* lm_in_b  = (const float*)d_in[11];
    const float* lm_out_w = (const float*)d_in[12];
    const float* lm_out_b = (const float*)d_in[13];
    const float* ta_in_w  = (const float*)d_in[14];
    const float* ta_in_b  = (const float*)d_in[15];
    const float* ta_out_w = (const float*)d_in[16];
    const float* ta_out_b = (const float*)d_in[17];
    float* out = (float*)d_out;

    cudaFuncSetAttribute(ode_main, cudaFuncAttributeMaxDynamicSharedMemorySize, SMEM_BYTES);

    prep1<<<1, 256>>>(t, W0, b0, lm_in_w, lm_in_b, lm_out_w, lm_out_b,
                      ta_in_b, ta_out_w, ta_out_b);
    prep2<<<64, 256>>>(ta_in_w, ta_out_w);
    ode_main<<<BATCHN / ROWS, NTHREADS, SMEM_BYTES>>>(
        state, W0, blkW1, blkb1, blkW2, blkb2, Wout, bout, out);
}